// round 1
// baseline (speedup 1.0000x reference)
#include <cuda_runtime.h>

// Problem constants
#define BB 16
#define NTOK 2049
#define NK 2048        // logits per batch
#define CC 1024
#define WS 3072        // w_qkv row stride (3*C)

// Scratch (no allocation allowed -> __device__ globals)
__device__ float g_qcls[BB * CC];
__device__ float g_v[BB * CC];

// ---------------------------------------------------------------------------
// K1: q_cls[b,c] = sum_d x[b,0,d] * W[d, c]   (W_q = cols 0..1023 of w_qkv)
// grid (8 c-tiles, 16 b), 128 threads. x row cached in smem, W loads coalesced.
// ---------------------------------------------------------------------------
__global__ void k_qcls(const float* __restrict__ x, const float* __restrict__ w) {
    __shared__ float xs[CC];
    const int b = blockIdx.y;
    const int c = blockIdx.x * 128 + threadIdx.x;
    const float* xrow = x + (size_t)b * NTOK * CC;   // token 0
    for (int i = threadIdx.x; i < CC; i += 128) xs[i] = xrow[i];
    __syncthreads();

    const float* wc = w + c;
    float a0 = 0.f, a1 = 0.f, a2 = 0.f, a3 = 0.f;
    #pragma unroll 4
    for (int d = 0; d < CC; d += 4) {
        a0 = fmaf(xs[d + 0], wc[(size_t)(d + 0) * WS], a0);
        a1 = fmaf(xs[d + 1], wc[(size_t)(d + 1) * WS], a1);
        a2 = fmaf(xs[d + 2], wc[(size_t)(d + 2) * WS], a2);
        a3 = fmaf(xs[d + 3], wc[(size_t)(d + 3) * WS], a3);
    }
    g_qcls[b * CC + c] = (a0 + a1) + (a2 + a3);
}

// ---------------------------------------------------------------------------
// K2: v[b,d] = sum_c W[d, 1024 + c] * q_cls[b,c]
// One warp per d handles 8 batches (b-group). grid (128 d-blocks, 2 b-groups),
// 256 threads = 8 warps. q_cls slice (8*1024 f32 = 32KB) in smem.
// ---------------------------------------------------------------------------
__global__ void k_v(const float* __restrict__ w) {
    __shared__ float qs[8 * CC];
    const int bg   = blockIdx.y;                    // 0..1
    const int d    = blockIdx.x * 8 + (threadIdx.x >> 5);
    const int lane = threadIdx.x & 31;

    for (int i = threadIdx.x; i < 8 * CC; i += 256)
        qs[i] = g_qcls[bg * 8 * CC + i];
    __syncthreads();

    const float* wr = w + (size_t)d * WS + CC;      // W_k row d
    float acc[8];
    #pragma unroll
    for (int b = 0; b < 8; b++) acc[b] = 0.f;

    #pragma unroll 4
    for (int i = 0; i < 32; i++) {
        const int c = lane + 32 * i;
        const float wv = wr[c];
        #pragma unroll
        for (int b = 0; b < 8; b++)
            acc[b] = fmaf(wv, qs[b * CC + c], acc[b]);
    }
    #pragma unroll
    for (int b = 0; b < 8; b++) {
        float a = acc[b];
        #pragma unroll
        for (int o = 16; o; o >>= 1) a += __shfl_xor_sync(0xffffffffu, a, o);
        if (lane == 0) g_v[(bg * 8 + b) * CC + d] = a;
    }
}

// ---------------------------------------------------------------------------
// K3 (dominant, HBM-bound): logits[b,n] = scale * x[b,n+1,:] . v[b,:]
// One warp per (b,n); float4 loads, 8 iters, warp shuffle reduce.
// grid 4096 x 256 threads. Writes scaled logits straight into d_out.
// ---------------------------------------------------------------------------
__global__ void k_logits(const float* __restrict__ x, float* __restrict__ out) {
    const int wid  = (blockIdx.x * 256 + threadIdx.x) >> 5;  // 0..32767
    const int lane = threadIdx.x & 31;
    const int b = wid >> 11;          // /2048
    const int n = wid & (NK - 1);

    const float4* xr = (const float4*)(x + ((size_t)b * NTOK + (n + 1)) * CC);
    const float4* vr = (const float4*)(g_v + b * CC);

    float a0 = 0.f, a1 = 0.f, a2 = 0.f, a3 = 0.f;
    #pragma unroll
    for (int i = 0; i < 8; i++) {
        const float4 xv = xr[lane + 32 * i];
        const float4 vv = vr[lane + 32 * i];
        a0 = fmaf(xv.x, vv.x, a0);
        a1 = fmaf(xv.y, vv.y, a1);
        a2 = fmaf(xv.z, vv.z, a2);
        a3 = fmaf(xv.w, vv.w, a3);
    }
    float a = (a0 + a1) + (a2 + a3);
    #pragma unroll
    for (int o = 16; o; o >>= 1) a += __shfl_xor_sync(0xffffffffu, a, o);
    if (lane == 0) out[(b << 11) + n] = a * 0.03125f;   // scale = 1024^-0.5
}

// ---------------------------------------------------------------------------
// K4: in-place softmax over 2048 per batch. One block (1024 thr) per batch.
// ---------------------------------------------------------------------------
__global__ void k_softmax(float* __restrict__ out) {
    __shared__ float red[32];
    __shared__ float bc;
    const int b = blockIdx.x, t = threadIdx.x;
    float* p = out + (b << 11);

    float v0 = p[t], v1 = p[t + 1024];

    // block max
    float m = fmaxf(v0, v1);
    #pragma unroll
    for (int o = 16; o; o >>= 1) m = fmaxf(m, __shfl_xor_sync(0xffffffffu, m, o));
    if ((t & 31) == 0) red[t >> 5] = m;
    __syncthreads();
    if (t < 32) {
        float mm = red[t];
        #pragma unroll
        for (int o = 16; o; o >>= 1) mm = fmaxf(mm, __shfl_xor_sync(0xffffffffu, mm, o));
        if (t == 0) bc = mm;
    }
    __syncthreads();
    const float bmax = bc;

    const float e0 = expf(v0 - bmax);
    const float e1 = expf(v1 - bmax);

    // block sum
    float s = e0 + e1;
    #pragma unroll
    for (int o = 16; o; o >>= 1) s += __shfl_xor_sync(0xffffffffu, s, o);
    if ((t & 31) == 0) red[t >> 5] = s;
    __syncthreads();
    if (t < 32) {
        float ss = red[t];
        #pragma unroll
        for (int o = 16; o; o >>= 1) ss += __shfl_xor_sync(0xffffffffu, ss, o);
        if (t == 0) bc = ss;
    }
    __syncthreads();

    const float inv = 1.0f / bc;
    p[t]        = e0 * inv;
    p[t + 1024] = e1 * inv;
}

// ---------------------------------------------------------------------------
extern "C" void kernel_launch(void* const* d_in, const int* in_sizes, int n_in,
                              void* d_out, int out_size) {
    const float* x = (const float*)d_in[0];
    const float* w = (const float*)d_in[1];
    // defensive: detect swapped input order by size (w_qkv = 1024*3072)
    if (n_in >= 2 && in_sizes[0] == CC * WS && in_sizes[1] == BB * NTOK * CC) {
        x = (const float*)d_in[1];
        w = (const float*)d_in[0];
    }
    float* out = (float*)d_out;

    k_qcls   <<<dim3(8, 16),  128>>>(x, w);
    k_v      <<<dim3(128, 2), 256>>>(w);
    k_logits <<<4096,         256>>>(x, out);
    k_softmax<<<BB,          1024>>>(out);
}

// round 2
// speedup vs baseline: 2.1682x; 2.1682x over previous
#include <cuda_runtime.h>

#define BB 16
#define NTOK 2049
#define NK 2048
#define CC 1024
#define WS 3072

__device__ float g_qcls[BB * CC];
__device__ float g_v[BB * CC];

// ---------------------------------------------------------------------------
// K1: q_cls[b,c] = sum_d x[b,0,d] * W[d,c]  (W_q = cols 0..1023)
// grid (8 c-tiles, 16 b), 512 threads = 16 warps. Warp ws owns d-range
// [ws*64, ws*64+64); lane covers 4 consecutive c via LDG.128.
// Deterministic smem reduction over the 16 d-slices.
// ---------------------------------------------------------------------------
__global__ __launch_bounds__(512) void k_qcls(const float* __restrict__ x,
                                              const float* __restrict__ w) {
    __shared__ float xs[CC];
    __shared__ float red[16 * 128];
    const int b     = blockIdx.y;
    const int tid   = threadIdx.x;
    const int ws    = tid >> 5;            // d-slice 0..15
    const int lane  = tid & 31;
    const int c     = blockIdx.x * 128 + lane * 4;

    const float* xrow = x + (size_t)b * NTOK * CC;   // token 0
    xs[tid]       = xrow[tid];
    xs[tid + 512] = xrow[tid + 512];
    __syncthreads();

    float4 acc = make_float4(0.f, 0.f, 0.f, 0.f);
    const int d0 = ws * 64;
    #pragma unroll
    for (int i = 0; i < 16; i++) {
        const int d = d0 + i * 4;
        const float4 xv = *(const float4*)&xs[d];
        const float4 w0 = *(const float4*)&w[(size_t)(d + 0) * WS + c];
        const float4 w1 = *(const float4*)&w[(size_t)(d + 1) * WS + c];
        const float4 w2 = *(const float4*)&w[(size_t)(d + 2) * WS + c];
        const float4 w3 = *(const float4*)&w[(size_t)(d + 3) * WS + c];
        acc.x = fmaf(xv.x, w0.x, acc.x); acc.y = fmaf(xv.x, w0.y, acc.y);
        acc.z = fmaf(xv.x, w0.z, acc.z); acc.w = fmaf(xv.x, w0.w, acc.w);
        acc.x = fmaf(xv.y, w1.x, acc.x); acc.y = fmaf(xv.y, w1.y, acc.y);
        acc.z = fmaf(xv.y, w1.z, acc.z); acc.w = fmaf(xv.y, w1.w, acc.w);
        acc.x = fmaf(xv.z, w2.x, acc.x); acc.y = fmaf(xv.z, w2.y, acc.y);
        acc.z = fmaf(xv.z, w2.z, acc.z); acc.w = fmaf(xv.z, w2.w, acc.w);
        acc.x = fmaf(xv.w, w3.x, acc.x); acc.y = fmaf(xv.w, w3.y, acc.y);
        acc.z = fmaf(xv.w, w3.z, acc.z); acc.w = fmaf(xv.w, w3.w, acc.w);
    }
    *(float4*)&red[ws * 128 + lane * 4] = acc;
    __syncthreads();

    if (tid < 128) {
        float s = 0.f;
        #pragma unroll
        for (int k = 0; k < 16; k++) s += red[k * 128 + tid];
        g_qcls[b * CC + blockIdx.x * 128 + tid] = s;
    }
}

// ---------------------------------------------------------------------------
// K2: v[b,d] = W_k[d,:] . q_cls[b,:]   (W_k = cols 1024..2047, row-contiguous)
// grid (128 d-blocks, 2 b-groups of 8), 256 thr = 8 warps, warp per d.
// q_cls slice (8*1024 f32 = 32KB) in smem; float4 everywhere.
// ---------------------------------------------------------------------------
__global__ __launch_bounds__(256) void k_v(const float* __restrict__ w) {
    __shared__ float qs[8 * CC];
    const int bg   = blockIdx.y;
    const int d    = blockIdx.x * 8 + (threadIdx.x >> 5);
    const int lane = threadIdx.x & 31;

    #pragma unroll
    for (int i = 0; i < 8; i++)
        ((float4*)qs)[threadIdx.x + 256 * i] =
            ((const float4*)(g_qcls + bg * 8 * CC))[threadIdx.x + 256 * i];
    __syncthreads();

    const float* wr = w + (size_t)d * WS + CC;
    float acc[8];
    #pragma unroll
    for (int b = 0; b < 8; b++) acc[b] = 0.f;

    #pragma unroll
    for (int i = 0; i < 8; i++) {
        const int cc = i * 128 + lane * 4;
        const float4 w4 = *(const float4*)&wr[cc];
        #pragma unroll
        for (int b = 0; b < 8; b++) {
            const float4 q4 = *(const float4*)&qs[b * CC + cc];
            acc[b] = fmaf(w4.x, q4.x, acc[b]);
            acc[b] = fmaf(w4.y, q4.y, acc[b]);
            acc[b] = fmaf(w4.z, q4.z, acc[b]);
            acc[b] = fmaf(w4.w, q4.w, acc[b]);
        }
    }
    #pragma unroll
    for (int b = 0; b < 8; b++) {
        float a = acc[b];
        #pragma unroll
        for (int o = 16; o; o >>= 1) a += __shfl_xor_sync(0xffffffffu, a, o);
        if (lane == 0) g_v[(bg * 8 + b) * CC + d] = a;
    }
}

// ---------------------------------------------------------------------------
// K3 (dominant, HBM-bound): logits[b,n] = scale * x[b,n+1,:] . v[b,:]
// Block = 256 thr (8 warps), each warp does 2 rows -> 16 rows/block.
// v[b] cached in smem once per block. grid (128, 16).
// ---------------------------------------------------------------------------
__global__ __launch_bounds__(256) void k_logits(const float* __restrict__ x,
                                                float* __restrict__ out) {
    __shared__ float vs[CC];
    const int b    = blockIdx.y;
    const int warp = threadIdx.x >> 5;
    const int lane = threadIdx.x & 31;

    ((float4*)vs)[threadIdx.x] = ((const float4*)(g_v + b * CC))[threadIdx.x];
    __syncthreads();

    const int n0 = blockIdx.x * 16 + warp * 2;     // logit indices n0, n0+1
    const float* x0 = x + ((size_t)b * NTOK + (n0 + 1)) * CC;   // token n0+1
    const float* x1 = x0 + CC;

    float4 a0 = make_float4(0.f, 0.f, 0.f, 0.f);
    float4 a1 = make_float4(0.f, 0.f, 0.f, 0.f);
    #pragma unroll
    for (int i = 0; i < 8; i++) {
        const int cc = i * 128 + lane * 4;
        const float4 xv0 = *(const float4*)&x0[cc];
        const float4 xv1 = *(const float4*)&x1[cc];
        const float4 vv  = *(const float4*)&vs[cc];
        a0.x = fmaf(xv0.x, vv.x, a0.x); a0.y = fmaf(xv0.y, vv.y, a0.y);
        a0.z = fmaf(xv0.z, vv.z, a0.z); a0.w = fmaf(xv0.w, vv.w, a0.w);
        a1.x = fmaf(xv1.x, vv.x, a1.x); a1.y = fmaf(xv1.y, vv.y, a1.y);
        a1.z = fmaf(xv1.z, vv.z, a1.z); a1.w = fmaf(xv1.w, vv.w, a1.w);
    }
    float s0 = (a0.x + a0.y) + (a0.z + a0.w);
    float s1 = (a1.x + a1.y) + (a1.z + a1.w);
    #pragma unroll
    for (int o = 16; o; o >>= 1) {
        s0 += __shfl_xor_sync(0xffffffffu, s0, o);
        s1 += __shfl_xor_sync(0xffffffffu, s1, o);
    }
    if (lane == 0) {
        out[(b << 11) + n0]     = s0 * 0.03125f;
        out[(b << 11) + n0 + 1] = s1 * 0.03125f;
    }
}

// ---------------------------------------------------------------------------
// K4: in-place softmax over 2048 per batch. 512 thr, float4/thread, __expf.
// ---------------------------------------------------------------------------
__global__ __launch_bounds__(512) void k_softmax(float* __restrict__ out) {
    __shared__ float red[16];
    __shared__ float bc;
    const int b = blockIdx.x, t = threadIdx.x;
    float4* p = (float4*)(out + (b << 11));

    float4 v = p[t];

    float m = fmaxf(fmaxf(v.x, v.y), fmaxf(v.z, v.w));
    #pragma unroll
    for (int o = 16; o; o >>= 1) m = fmaxf(m, __shfl_xor_sync(0xffffffffu, m, o));
    if ((t & 31) == 0) red[t >> 5] = m;
    __syncthreads();
    if (t < 16) {
        float mm = red[t];
        #pragma unroll
        for (int o = 8; o; o >>= 1) mm = fmaxf(mm, __shfl_xor_sync(0xffffu, mm, o));
        if (t == 0) bc = mm;
    }
    __syncthreads();
    const float bmax = bc;

    float4 e;
    e.x = __expf(v.x - bmax); e.y = __expf(v.y - bmax);
    e.z = __expf(v.z - bmax); e.w = __expf(v.w - bmax);

    float s = (e.x + e.y) + (e.z + e.w);
    #pragma unroll
    for (int o = 16; o; o >>= 1) s += __shfl_xor_sync(0xffffffffu, s, o);
    if ((t & 31) == 0) red[t >> 5] = s;
    __syncthreads();
    if (t < 16) {
        float ss = red[t];
        #pragma unroll
        for (int o = 8; o; o >>= 1) ss += __shfl_xor_sync(0xffffu, ss, o);
        if (t == 0) bc = ss;
    }
    __syncthreads();

    const float inv = 1.0f / bc;
    e.x *= inv; e.y *= inv; e.z *= inv; e.w *= inv;
    p[t] = e;
}

// ---------------------------------------------------------------------------
extern "C" void kernel_launch(void* const* d_in, const int* in_sizes, int n_in,
                              void* d_out, int out_size) {
    const float* x = (const float*)d_in[0];
    const float* w = (const float*)d_in[1];
    if (n_in >= 2 && in_sizes[0] == CC * WS && in_sizes[1] == BB * NTOK * CC) {
        x = (const float*)d_in[1];
        w = (const float*)d_in[0];
    }
    float* out = (float*)d_out;

    k_qcls   <<<dim3(8, 16),   512>>>(x, w);
    k_v      <<<dim3(128, 2),  256>>>(w);
    k_logits <<<dim3(128, 16), 256>>>(x, out);
    k_softmax<<<BB,            512>>>(out);
}

// round 3
// speedup vs baseline: 2.3090x; 1.0649x over previous
#include <cuda_runtime.h>

#define BB 16
#define NTOK 2049
#define NK 2048
#define CC 1024
#define WS 3072

__device__ float g_qp[16 * BB * CC];   // q_cls partials: [dslice][b][c]
__device__ float g_qcls[BB * CC];
__device__ float g_v[BB * CC];
__device__ float g_psum[BB * 128];     // exp partial sums: [b][xblock]

// ---------------------------------------------------------------------------
// K1: q_cls partials. grid (8 c-tiles, 16 d-slices), 256 thr.
// Each block: all 16 batches, 128 c, 64 d. W_q read exactly once chip-wide.
// 8 warps = 4 d-groups x 2 b-groups; smem reduction over d-groups.
// ---------------------------------------------------------------------------
__global__ __launch_bounds__(256) void k_qcls(const float* __restrict__ x,
                                              const float* __restrict__ w) {
    __shared__ float xs[16 * 64];        // [b][dd]
    __shared__ float red[4 * 16 * 128];  // [dg][b][c] 32KB
    const int t  = threadIdx.x;
    const int d0 = blockIdx.y * 64;
    const int c0 = blockIdx.x * 128;

    {   // stage x token-0 slices: 1024 floats = 256 float4
        const int b = t >> 4, dd = (t & 15) * 4;
        *(float4*)&xs[b * 64 + dd] =
            *(const float4*)&x[(size_t)b * NTOK * CC + d0 + dd];
    }
    __syncthreads();

    const int wid = t >> 5, lane = t & 31;
    const int dg = wid & 3, bg = wid >> 2;
    const int c = c0 + lane * 4;

    float4 a[8];
    #pragma unroll
    for (int j = 0; j < 8; j++) a[j] = make_float4(0.f, 0.f, 0.f, 0.f);

    const float* xb = &xs[bg * 8 * 64];
    #pragma unroll
    for (int i = 0; i < 16; i++) {
        const int dd = dg * 16 + i;
        const float4 w4 = *(const float4*)&w[(size_t)(d0 + dd) * WS + c];
        #pragma unroll
        for (int j = 0; j < 8; j++) {
            const float xv = xb[j * 64 + dd];
            a[j].x = fmaf(w4.x, xv, a[j].x);
            a[j].y = fmaf(w4.y, xv, a[j].y);
            a[j].z = fmaf(w4.z, xv, a[j].z);
            a[j].w = fmaf(w4.w, xv, a[j].w);
        }
    }
    #pragma unroll
    for (int j = 0; j < 8; j++)
        *(float4*)&red[dg * 2048 + (bg * 8 + j) * 128 + lane * 4] = a[j];
    __syncthreads();

    #pragma unroll
    for (int k = 0; k < 8; k++) {
        const int idx = t + 256 * k;                 // b = idx>>7, c = idx&127
        const float s = (red[idx] + red[idx + 2048])
                      + (red[idx + 4096] + red[idx + 6144]);
        g_qp[(blockIdx.y * 16 + (idx >> 7)) * CC + c0 + (idx & 127)] = s;
    }
}

// ---------------------------------------------------------------------------
// K1b: collapse 16 d-slice partials -> g_qcls. grid (8,16), 128 thr.
// ---------------------------------------------------------------------------
__global__ __launch_bounds__(128) void k_qred() {
    const int b = blockIdx.y;
    const int c = blockIdx.x * 128 + threadIdx.x;
    float s = 0.f;
    #pragma unroll
    for (int ds = 0; ds < 16; ds++) s += g_qp[(ds * 16 + b) * CC + c];
    g_qcls[b * CC + c] = s;
}

// ---------------------------------------------------------------------------
// K2: v[b,d] = W_k[d,:] . q_cls[b,:]  (rows 1024..2047 of w columns; row-contig)
// grid (128 d-blocks, 2 b-groups), 256 thr, warp per d, 8 batches/warp.
// ---------------------------------------------------------------------------
__global__ __launch_bounds__(256) void k_v(const float* __restrict__ w) {
    __shared__ float qs[8 * CC];
    const int bg   = blockIdx.y;
    const int d    = blockIdx.x * 8 + (threadIdx.x >> 5);
    const int lane = threadIdx.x & 31;

    #pragma unroll
    for (int i = 0; i < 8; i++)
        ((float4*)qs)[threadIdx.x + 256 * i] =
            ((const float4*)(g_qcls + bg * 8 * CC))[threadIdx.x + 256 * i];
    __syncthreads();

    const float* wr = w + (size_t)d * WS + CC;
    float acc[8];
    #pragma unroll
    for (int b = 0; b < 8; b++) acc[b] = 0.f;

    #pragma unroll
    for (int i = 0; i < 8; i++) {
        const int cc = i * 128 + lane * 4;
        const float4 w4 = *(const float4*)&wr[cc];
        #pragma unroll
        for (int b = 0; b < 8; b++) {
            const float4 q4 = *(const float4*)&qs[b * CC + cc];
            acc[b] = fmaf(w4.x, q4.x, acc[b]);
            acc[b] = fmaf(w4.y, q4.y, acc[b]);
            acc[b] = fmaf(w4.z, q4.z, acc[b]);
            acc[b] = fmaf(w4.w, q4.w, acc[b]);
        }
    }
    #pragma unroll
    for (int b = 0; b < 8; b++) {
        float a = acc[b];
        #pragma unroll
        for (int o = 16; o; o >>= 1) a += __shfl_xor_sync(0xffffffffu, a, o);
        if (lane == 0) g_v[(bg * 8 + b) * CC + d] = a;
    }
}

// ---------------------------------------------------------------------------
// K3 (dominant, HBM-bound): out[b,n] = exp(scale * x[b,n+1,:].v[b,:])
// plus deterministic per-block partial sums into g_psum.
// Block = 256 thr (8 warps x 2 rows = 16 rows). grid (128, 16).
// ---------------------------------------------------------------------------
__global__ __launch_bounds__(256) void k_logits(const float* __restrict__ x,
                                                float* __restrict__ out) {
    __shared__ float vs[CC];
    __shared__ float esum[8];
    const int b    = blockIdx.y;
    const int warp = threadIdx.x >> 5;
    const int lane = threadIdx.x & 31;

    ((float4*)vs)[threadIdx.x] = ((const float4*)(g_v + b * CC))[threadIdx.x];
    __syncthreads();

    const int n0 = blockIdx.x * 16 + warp * 2;
    const float4* x0 = (const float4*)(x + ((size_t)b * NTOK + (n0 + 1)) * CC);
    const float4* x1 = (const float4*)((const float*)x0 + CC);

    float4 a0 = make_float4(0.f, 0.f, 0.f, 0.f);
    float4 a1 = make_float4(0.f, 0.f, 0.f, 0.f);
    #pragma unroll
    for (int i = 0; i < 8; i++) {
        const int cc = i * 32 + lane;
        const float4 xv0 = __ldcs(&x0[cc]);
        const float4 xv1 = __ldcs(&x1[cc]);
        const float4 vv  = *(const float4*)&vs[cc * 4];
        a0.x = fmaf(xv0.x, vv.x, a0.x); a0.y = fmaf(xv0.y, vv.y, a0.y);
        a0.z = fmaf(xv0.z, vv.z, a0.z); a0.w = fmaf(xv0.w, vv.w, a0.w);
        a1.x = fmaf(xv1.x, vv.x, a1.x); a1.y = fmaf(xv1.y, vv.y, a1.y);
        a1.z = fmaf(xv1.z, vv.z, a1.z); a1.w = fmaf(xv1.w, vv.w, a1.w);
    }
    float s0 = (a0.x + a0.y) + (a0.z + a0.w);
    float s1 = (a1.x + a1.y) + (a1.z + a1.w);
    #pragma unroll
    for (int o = 16; o; o >>= 1) {
        s0 += __shfl_xor_sync(0xffffffffu, s0, o);
        s1 += __shfl_xor_sync(0xffffffffu, s1, o);
    }
    if (lane == 0) {
        const float e0 = __expf(s0 * 0.03125f);
        const float e1 = __expf(s1 * 0.03125f);
        out[(b << 11) + n0]     = e0;
        out[(b << 11) + n0 + 1] = e1;
        esum[warp] = e0 + e1;
    }
    __syncthreads();
    if (threadIdx.x == 0) {
        const float tsum = ((esum[0] + esum[1]) + (esum[2] + esum[3]))
                         + ((esum[4] + esum[5]) + (esum[6] + esum[7]));
        g_psum[b * 128 + blockIdx.x] = tsum;
    }
}

// ---------------------------------------------------------------------------
// K4: normalize. grid (16 chunks, 16 b), 128 thr. Deterministic smem reduce
// of the 128 block partials, then scale 128 elements.
// ---------------------------------------------------------------------------
__global__ __launch_bounds__(128) void k_norm(float* __restrict__ out) {
    __shared__ float sp[128];
    const int b = blockIdx.y, t = threadIdx.x;
    sp[t] = g_psum[b * 128 + t];
    __syncthreads();
    #pragma unroll
    for (int o = 64; o; o >>= 1) {
        if (t < o) sp[t] += sp[t + o];
        __syncthreads();
    }
    const float inv = 1.0f / sp[0];
    const int idx = blockIdx.x * 128 + t;
    out[(b << 11) + idx] *= inv;
}

// ---------------------------------------------------------------------------
extern "C" void kernel_launch(void* const* d_in, const int* in_sizes, int n_in,
                              void* d_out, int out_size) {
    const float* x = (const float*)d_in[0];
    const float* w = (const float*)d_in[1];
    if (n_in >= 2 && in_sizes[0] == CC * WS && in_sizes[1] == BB * NTOK * CC) {
        x = (const float*)d_in[1];
        w = (const float*)d_in[0];
    }
    float* out = (float*)d_out;

    k_qcls  <<<dim3(8, 16),   256>>>(x, w);
    k_qred  <<<dim3(8, 16),   128>>>();
    k_v     <<<dim3(128, 2),  256>>>(w);
    k_logits<<<dim3(128, 16), 256>>>(x, out);
    k_norm  <<<dim3(16, 16),  128>>>(out);
}